// round 1
// baseline (speedup 1.0000x reference)
#include <cuda_runtime.h>
#include <math.h>

// Problem shape (fixed by the dataset)
#define S_TOT   258
#define C_DIM   64
#define H_DIM   64
#define W_DIM   64
#define HO      32
#define WO      32
#define NPIX    (C_DIM * H_DIM * W_DIM)     // 262144 pixels per layer
#define NPIX4   (NPIX / 4)                  // 65536 float4 per layer
#define NPIX2   (NPIX / 2)                  // float2 per layer
#define NWIN    (C_DIM * HO * WO)           // 65536 output windows (= out layer size)
#define NGROUP  8                           // S-split for the eps reduction

// output layout offsets (x_out, x_min, x_max, x_true_out concatenated)
#define OFF_XMIN   ((size_t)S_TOT * NWIN)               // 16908288
#define OFF_XMAX   (OFF_XMIN + NWIN)
#define OFF_XTRUE  (OFF_XMAX + NWIN)

// scratch: per-group partial sums of |x[s]| (deterministic, no atomics)
__device__ float4 g_partial[NGROUP * NPIX4];            // 8 MB

// ---------------------------------------------------------------------------
// Kernel 1: eps_abs partial reduction over symbol layers s = 1..257.
// Grid: (NPIX4/256, NGROUP). Each thread owns 4 consecutive pixels (float4)
// and one S-group (32 layers; last group gets 33). float4 loads, unroll 8.
// ---------------------------------------------------------------------------
__global__ void __launch_bounds__(256) k_eps_partial(const float4* __restrict__ x4) {
    const int p4 = blockIdx.x * 256 + threadIdx.x;      // 0..65535
    const int g  = blockIdx.y;                          // 0..7
    const int s0 = 1 + g * 32;
    const int ns = (g == NGROUP - 1) ? 33 : 32;         // 7*32 + 33 = 257

    const float4* p = x4 + (size_t)s0 * NPIX4 + p4;

    float ax = 0.f, ay = 0.f, az = 0.f, aw = 0.f;

    int i = 0;
    for (; i + 8 <= ns; i += 8) {
        float4 v0 = p[(size_t)(i + 0) * NPIX4];
        float4 v1 = p[(size_t)(i + 1) * NPIX4];
        float4 v2 = p[(size_t)(i + 2) * NPIX4];
        float4 v3 = p[(size_t)(i + 3) * NPIX4];
        float4 v4 = p[(size_t)(i + 4) * NPIX4];
        float4 v5 = p[(size_t)(i + 5) * NPIX4];
        float4 v6 = p[(size_t)(i + 6) * NPIX4];
        float4 v7 = p[(size_t)(i + 7) * NPIX4];
        ax += fabsf(v0.x); ay += fabsf(v0.y); az += fabsf(v0.z); aw += fabsf(v0.w);
        ax += fabsf(v1.x); ay += fabsf(v1.y); az += fabsf(v1.z); aw += fabsf(v1.w);
        ax += fabsf(v2.x); ay += fabsf(v2.y); az += fabsf(v2.z); aw += fabsf(v2.w);
        ax += fabsf(v3.x); ay += fabsf(v3.y); az += fabsf(v3.z); aw += fabsf(v3.w);
        ax += fabsf(v4.x); ay += fabsf(v4.y); az += fabsf(v4.z); aw += fabsf(v4.w);
        ax += fabsf(v5.x); ay += fabsf(v5.y); az += fabsf(v5.z); aw += fabsf(v5.w);
        ax += fabsf(v6.x); ay += fabsf(v6.y); az += fabsf(v6.z); aw += fabsf(v6.w);
        ax += fabsf(v7.x); ay += fabsf(v7.y); az += fabsf(v7.z); aw += fabsf(v7.w);
    }
    for (; i < ns; i++) {
        float4 v = p[(size_t)i * NPIX4];
        ax += fabsf(v.x); ay += fabsf(v.y); az += fabsf(v.z); aw += fabsf(v.w);
    }

    g_partial[g * NPIX4 + p4] = make_float4(ax, ay, az, aw);
}

// ---------------------------------------------------------------------------
// Kernel 2: per-window decision + full output write.
// One thread per window (c, ho, wo). Window element order (jax pool_windows):
//   K index = dy*2 + dx  ->  [top.x, top.y, bot.x, bot.y]
// exact path is statistically dead for this input -> the gather loads are
// predicated and (almost) never issue; kernel is store-bandwidth bound.
// ---------------------------------------------------------------------------
__global__ void __launch_bounds__(256) k_finalize(const float* __restrict__ x,
                                                  const float* __restrict__ xtrue,
                                                  float* __restrict__ out) {
    const int win = blockIdx.x * 256 + threadIdx.x;     // 0..65535
    const int c  = win >> 10;
    const int ho = (win >> 5) & 31;
    const int wo = win & 31;
    const int h0 = 2 * ho;
    const int h1 = h0 + 1;

    // float2 indices of the window's top/bottom 2-element segments
    const int r0 = (c * H_DIM + h0) * (W_DIM / 2) + wo;
    const int r1 = (c * H_DIM + h1) * (W_DIM / 2) + wo;

    const float2* x2 = (const float2*)x;
    const float2 t0 = x2[r0];   // x[0] top pair
    const float2 b0 = x2[r1];   // x[0] bottom pair

    // Reduce the 8 group partials -> eps_abs for the 4 pixels
    const float2* pp = (const float2*)g_partial;
    float etx = 0.f, ety = 0.f, ebx = 0.f, eby = 0.f;
#pragma unroll
    for (int g = 0; g < NGROUP; g++) {
        float2 a = pp[(size_t)g * NPIX2 + r0];
        float2 b = pp[(size_t)g * NPIX2 + r1];
        etx += a.x; ety += a.y; ebx += b.x; eby += b.y;
    }

    float lo0 = t0.x - etx, lo1 = t0.y - ety, lo2 = b0.x - ebx, lo3 = b0.y - eby;
    float hi0 = t0.x + etx, hi1 = t0.y + ety, hi2 = b0.x + ebx, hi3 = b0.y + eby;

    // argmax of lower bounds, first occurrence wins (matches jnp.argmax)
    int   istar = 0;
    float lbest = lo0;
    if (lo1 > lbest) { lbest = lo1; istar = 1; }
    if (lo2 > lbest) { lbest = lo2; istar = 2; }
    if (lo3 > lbest) { lbest = lo3; istar = 3; }

    const float umax = fmaxf(fmaxf(hi0, hi1), fmaxf(hi2, hi3));

    float uo = -3.0e38f;
    if (istar != 0) uo = fmaxf(uo, hi0);
    if (istar != 1) uo = fmaxf(uo, hi1);
    if (istar != 2) uo = fmaxf(uo, hi2);
    if (istar != 3) uo = fmaxf(uo, hi3);

    const bool exact = (lbest >= uo);

    const float boxc = 0.5f * (lbest + umax);
    const float boxn = 0.5f * (umax - lbest);

    // chosen pixel global offset within a layer
    const int dy = istar >> 1;
    const int dx = istar & 1;
    const size_t poff = ((size_t)c * H_DIM + (h0 + dy)) * W_DIM + (2 * wo + dx);

    float center, noise, xmn, xmx;
    if (exact) {
        const float x0g  = (istar == 0) ? t0.x : (istar == 1) ? t0.y
                         : (istar == 2) ? b0.x : b0.y;
        const float epsg = (istar == 0) ? etx  : (istar == 1) ? ety
                         : (istar == 2) ? ebx  : eby;
        center = x0g;
        noise  = fabsf(x[(size_t)(S_TOT - 1) * NPIX + poff]);
        xmn = center - epsg;          // = l_star
        xmx = center + epsg;          // = u[i_star]
    } else {
        center = boxc;
        noise  = boxn;
        xmn = boxc - boxn;            // matches reference arithmetic
        xmx = boxc + boxn;
    }

    // scalar outputs
    out[win]                              = center;   // s = 0
    out[(size_t)(S_TOT - 1) * NWIN + win] = noise;    // s = 257
    out[OFF_XMIN + win]  = xmn;
    out[OFF_XMAX + win]  = xmx;

    // x_true max-pool
    const float2* xt2 = (const float2*)xtrue;
    const float2 tt = xt2[r0];
    const float2 tb = xt2[r1];
    out[OFF_XTRUE + win] = fmaxf(fmaxf(tt.x, tt.y), fmaxf(tb.x, tb.y));

    // eps rows s = 1..256: zero unless exact (predicated gather, ~never taken)
    float* o = out + NWIN + win;
    const float* xg = x + NPIX + poff;    // x[1] at chosen pixel
#pragma unroll 8
    for (int s = 1; s <= S_TOT - 2; s++) {
        float v = 0.f;
        if (exact) v = xg[(size_t)(s - 1) * NPIX];
        *o = v;
        o += NWIN;
    }
}

extern "C" void kernel_launch(void* const* d_in, const int* in_sizes, int n_in,
                              void* d_out, int out_size) {
    const float* x  = (const float*)d_in[0];
    const float* xt = (const float*)d_in[1];
    float* out = (float*)d_out;
    (void)in_sizes; (void)n_in; (void)out_size;

    dim3 g1(NPIX4 / 256, NGROUP);
    k_eps_partial<<<g1, 256>>>((const float4*)x);
    k_finalize<<<NWIN / 256, 256>>>(x, xt, out);
}